// round 2
// baseline (speedup 1.0000x reference)
#include <cuda_runtime.h>
#include <math.h>

#define B_  4
#define S_  2048
#define D_  1024
#define H_  16
#define DK_ 64

// Scratch (allocation-free rule: __device__ globals)
__device__ float g_Q[(size_t)B_ * S_ * D_];
__device__ float g_K[(size_t)B_ * S_ * D_];
__device__ float g_V[(size_t)B_ * S_ * D_];
__device__ float g_A[(size_t)B_ * S_ * D_];

// ---------------------------------------------------------------------------
// GEMM: C[M,N] = A[M,K] @ W[N,K]^T   (both K-contiguous, row-major)
// 128x128 block tile, BK=16, 256 threads, 8x8 micro-tile per thread.
// ---------------------------------------------------------------------------
#define GBM 128
#define GBN 128
#define GBK 16

__global__ __launch_bounds__(256) void gemm_awt(
    const float* __restrict__ A, const float* __restrict__ W,
    float* __restrict__ C, int M, int N, int K)
{
    __shared__ float As[GBK][GBM + 4];  // [k][m]
    __shared__ float Ws[GBK][GBN + 4];  // [k][n]

    const int tid = threadIdx.x;
    const int tr  = tid >> 4;   // 0..15  (row group)
    const int tc  = tid & 15;   // 0..15  (col group)
    const int bm  = blockIdx.y * GBM;
    const int bn  = blockIdx.x * GBN;

    float acc[8][8];
#pragma unroll
    for (int i = 0; i < 8; i++)
#pragma unroll
        for (int j = 0; j < 8; j++) acc[i][j] = 0.f;

    for (int k0 = 0; k0 < K; k0 += GBK) {
        // Load tiles (transposed into [k][m] / [k][n])
#pragma unroll
        for (int i = 0; i < 2; i++) {
            int idx = tid + i * 256;      // 0..511
            int row = idx >> 2;           // 0..127
            int c4  = (idx & 3) * 4;      // 0,4,8,12
            float4 va = *(const float4*)(A + (size_t)(bm + row) * K + k0 + c4);
            As[c4 + 0][row] = va.x; As[c4 + 1][row] = va.y;
            As[c4 + 2][row] = va.z; As[c4 + 3][row] = va.w;
            float4 vw = *(const float4*)(W + (size_t)(bn + row) * K + k0 + c4);
            Ws[c4 + 0][row] = vw.x; Ws[c4 + 1][row] = vw.y;
            Ws[c4 + 2][row] = vw.z; Ws[c4 + 3][row] = vw.w;
        }
        __syncthreads();

#pragma unroll
        for (int kk = 0; kk < GBK; kk++) {
            float a[8], b[8];
            *(float4*)(a)     = *(const float4*)&As[kk][tr * 8];
            *(float4*)(a + 4) = *(const float4*)&As[kk][tr * 8 + 4];
            *(float4*)(b)     = *(const float4*)&Ws[kk][tc * 8];
            *(float4*)(b + 4) = *(const float4*)&Ws[kk][tc * 8 + 4];
#pragma unroll
            for (int i = 0; i < 8; i++)
#pragma unroll
                for (int j = 0; j < 8; j++)
                    acc[i][j] += a[i] * b[j];
        }
        __syncthreads();
    }

#pragma unroll
    for (int i = 0; i < 8; i++) {
        float* cp = C + (size_t)(bm + tr * 8 + i) * N + bn + tc * 8;
        float4 v0 = make_float4(acc[i][0], acc[i][1], acc[i][2], acc[i][3]);
        float4 v1 = make_float4(acc[i][4], acc[i][5], acc[i][6], acc[i][7]);
        *(float4*)(cp)     = v0;
        *(float4*)(cp + 4) = v1;
    }
}

// ---------------------------------------------------------------------------
// Causal flash attention: per (b,h), 64-query tile, 64-key tiles,
// online softmax, 256 threads, 4x4 micro-tiles. Causal tile skipping:
// q-tile qt only visits k-tiles 0..qt.
// Layout: Q/K/V/O all [B*S, D] with head h occupying cols [h*64, h*64+64).
// ---------------------------------------------------------------------------
#define AT 64
#define AP (AT + 4)  // 68, keeps 16B alignment for float4 smem access

__global__ __launch_bounds__(256) void attn_kernel(
    const float* __restrict__ Q, const float* __restrict__ K,
    const float* __restrict__ V, float* __restrict__ O)
{
    extern __shared__ float sm[];
    float (*Qs)[AP] = (float (*)[AP])(sm);             // [d][q]
    float (*Ks)[AP] = (float (*)[AP])(sm + 64 * AP);   // [d][k]
    float (*Vs)[AP] = (float (*)[AP])(sm + 2 * 64 * AP); // [k][d]
    float (*Ps)[AP] = (float (*)[AP])(sm + 3 * 64 * AP); // [k][q]

    const int tid = threadIdx.x;
    const int tr  = tid >> 4;   // q group 0..15
    const int tc  = tid & 15;   // k/d group 0..15
    const int bh  = blockIdx.y;
    const int b   = bh >> 4;
    const int h   = bh & 15;
    const int q0  = blockIdx.x * AT;

    const float* Qp = Q + (size_t)b * S_ * D_ + (size_t)h * DK_;
    const float* Kp = K + (size_t)b * S_ * D_ + (size_t)h * DK_;
    const float* Vp = V + (size_t)b * S_ * D_ + (size_t)h * DK_;
    float*       Op = O + (size_t)b * S_ * D_ + (size_t)h * DK_;

    // Load Q tile transposed to [d][q]
#pragma unroll
    for (int i = 0; i < 4; i++) {
        int idx = tid + i * 256;     // 0..1023
        int row = idx >> 4;          // 0..63
        int c4  = (idx & 15) * 4;    // 0..60
        float4 v = *(const float4*)(Qp + (size_t)(q0 + row) * D_ + c4);
        Qs[c4 + 0][row] = v.x; Qs[c4 + 1][row] = v.y;
        Qs[c4 + 2][row] = v.z; Qs[c4 + 3][row] = v.w;
    }

    float acc[4][4];
#pragma unroll
    for (int i = 0; i < 4; i++)
#pragma unroll
        for (int j = 0; j < 4; j++) acc[i][j] = 0.f;
    float mi[4], li[4];
#pragma unroll
    for (int i = 0; i < 4; i++) { mi[i] = -1e30f; li[i] = 0.f; }

    const int last_kt = blockIdx.x;   // causal: tiles 0..blockIdx.x
    const float sc = 0.125f;          // 1/sqrt(64)

    for (int kt = 0; kt <= last_kt; kt++) {
        const int k0 = kt * AT;
        __syncthreads();  // Q tile visible (iter 0); Ps/Vs consumed (iters>0)

        // Load K transposed [d][k], V natural [k][d]
#pragma unroll
        for (int i = 0; i < 4; i++) {
            int idx = tid + i * 256;
            int row = idx >> 4;
            int c4  = (idx & 15) * 4;
            float4 vk = *(const float4*)(Kp + (size_t)(k0 + row) * D_ + c4);
            Ks[c4 + 0][row] = vk.x; Ks[c4 + 1][row] = vk.y;
            Ks[c4 + 2][row] = vk.z; Ks[c4 + 3][row] = vk.w;
            float4 vv = *(const float4*)(Vp + (size_t)(k0 + row) * D_ + c4);
            *(float4*)&Vs[row][c4] = vv;
        }
        __syncthreads();

        // S = Q @ K^T (contraction over d)
        float s[4][4];
#pragma unroll
        for (int i = 0; i < 4; i++)
#pragma unroll
            for (int j = 0; j < 4; j++) s[i][j] = 0.f;
#pragma unroll
        for (int d = 0; d < DK_; d++) {
            float a[4], bb[4];
            *(float4*)a  = *(const float4*)&Qs[d][tr * 4];
            *(float4*)bb = *(const float4*)&Ks[d][tc * 4];
#pragma unroll
            for (int i = 0; i < 4; i++)
#pragma unroll
                for (int j = 0; j < 4; j++)
                    s[i][j] += a[i] * bb[j];
        }

        // Scale + causal mask (only the diagonal tile needs masking)
        if (kt == last_kt) {
#pragma unroll
            for (int i = 0; i < 4; i++) {
                int qg = tr * 4 + i;
#pragma unroll
                for (int j = 0; j < 4; j++) {
                    int kg = tc * 4 + j;
                    s[i][j] = (kg <= qg) ? s[i][j] * sc : -1e30f;
                }
            }
        } else {
#pragma unroll
            for (int i = 0; i < 4; i++)
#pragma unroll
                for (int j = 0; j < 4; j++) s[i][j] *= sc;
        }

        // Online softmax. Row q spans the 16 tc-lanes (same half-warp:
        // lane = 16*(tr&1)+tc, so xor over bits 0..3 stays in-group).
#pragma unroll
        for (int i = 0; i < 4; i++) {
            float rm = fmaxf(fmaxf(s[i][0], s[i][1]), fmaxf(s[i][2], s[i][3]));
#pragma unroll
            for (int o = 8; o > 0; o >>= 1)
                rm = fmaxf(rm, __shfl_xor_sync(0xffffffffu, rm, o));
            float mnew = fmaxf(mi[i], rm);
            float p[4], rs = 0.f;
#pragma unroll
            for (int j = 0; j < 4; j++) {
                p[j] = __expf(s[i][j] - mnew);
                rs += p[j];
            }
#pragma unroll
            for (int o = 8; o > 0; o >>= 1)
                rs += __shfl_xor_sync(0xffffffffu, rs, o);
            float alpha = __expf(mi[i] - mnew);
            li[i] = li[i] * alpha + rs;
            mi[i] = mnew;
#pragma unroll
            for (int j = 0; j < 4; j++) acc[i][j] *= alpha;
            // Store P transposed [k][q] for the PV rank-1 loop
#pragma unroll
            for (int j = 0; j < 4; j++)
                Ps[tc * 4 + j][tr * 4 + i] = p[j];
        }
        __syncthreads();

        // O += P @ V (contraction over k)
#pragma unroll
        for (int kk = 0; kk < AT; kk++) {
            float a[4], bb[4];
            *(float4*)a  = *(const float4*)&Ps[kk][tr * 4];
            *(float4*)bb = *(const float4*)&Vs[kk][tc * 4];
#pragma unroll
            for (int i = 0; i < 4; i++)
#pragma unroll
                for (int j = 0; j < 4; j++)
                    acc[i][j] += a[i] * bb[j];
        }
    }

    // Epilogue: normalize by l and write
#pragma unroll
    for (int i = 0; i < 4; i++) {
        float inv = 1.0f / li[i];
        float4 o = make_float4(acc[i][0] * inv, acc[i][1] * inv,
                               acc[i][2] * inv, acc[i][3] * inv);
        *(float4*)(Op + (size_t)(q0 + tr * 4 + i) * D_ + tc * 4) = o;
    }
}

// ---------------------------------------------------------------------------
// Launch
// ---------------------------------------------------------------------------
#define ATTN_SMEM (4 * 64 * AP * (int)sizeof(float))   // 69632 B

extern "C" void kernel_launch(void* const* d_in, const int* in_sizes, int n_in,
                              void* d_out, int out_size)
{
    const float* x  = (const float*)d_in[0];
    const float* WQ = (const float*)d_in[1];
    const float* WK = (const float*)d_in[2];
    const float* WV = (const float*)d_in[3];
    const float* WO = (const float*)d_in[4];
    float* out = (float*)d_out;

    float *Qp, *Kp, *Vp, *Ap;
    cudaGetSymbolAddress((void**)&Qp, g_Q);
    cudaGetSymbolAddress((void**)&Kp, g_K);
    cudaGetSymbolAddress((void**)&Vp, g_V);
    cudaGetSymbolAddress((void**)&Ap, g_A);

    cudaFuncSetAttribute(attn_kernel,
                         cudaFuncAttributeMaxDynamicSharedMemorySize,
                         ATTN_SMEM);

    const int M = B_ * S_;                 // 8192
    dim3 gg(D_ / GBN, M / GBM);            // (8, 64)

    gemm_awt<<<gg, 256>>>(x, WQ, Qp, M, D_, D_);
    gemm_awt<<<gg, 256>>>(x, WK, Kp, M, D_, D_);
    gemm_awt<<<gg, 256>>>(x, WV, Vp, M, D_, D_);

    attn_kernel<<<dim3(S_ / AT, B_ * H_), 256, ATTN_SMEM>>>(Qp, Kp, Vp, Ap);

    gemm_awt<<<gg, 256>>>(Ap, WO, out, M, D_, D_);
}

// round 3
// speedup vs baseline: 1.6797x; 1.6797x over previous
#include <cuda_runtime.h>
#include <math.h>
#include <stdint.h>

#define B_  4
#define S_  2048
#define D_  1024
#define H_  16
#define DK_ 64

// Scratch (allocation-free rule: __device__ globals)
__device__ float g_Q[(size_t)B_ * S_ * D_];
__device__ float g_K[(size_t)B_ * S_ * D_];
__device__ float g_V[(size_t)B_ * S_ * D_];
__device__ float g_A[(size_t)B_ * S_ * D_];

// ---------------------------------------------------------------------------
// TF32 tensor-core GEMM: C[M,N] = A[M,K] @ W[N,K]^T
// Both operands K-contiguous == mma .row.col layout directly.
// Block 128x128, BK=32, 256 threads (8 warps, 2x4), warp tile 64x32.
// Smem row stride 36 floats -> all fragment LDS conflict-free.
// Double-buffered smem, cvt.rna.tf32 applied once at STS time.
// ---------------------------------------------------------------------------
#define TBM 128
#define TBN 128
#define TBK 32
#define TST 36                    // smem row stride (floats)
#define ASZ (TBM * TST)           // words per A stage
#define BSZ (TBN * TST)
#define GEMM_SMEM (2 * (ASZ + BSZ) * 4)   // 73728 B

__device__ __forceinline__ uint32_t f2tf32(float x) {
    uint32_t r;
    asm("cvt.rna.tf32.f32 %0, %1;" : "=r"(r) : "f"(x));
    return r;
}

__device__ __forceinline__ void mma_tf32(float c[4], const uint32_t a[4],
                                         const uint32_t b[2]) {
    asm volatile(
        "mma.sync.aligned.m16n8k8.row.col.f32.tf32.tf32.f32 "
        "{%0,%1,%2,%3}, {%4,%5,%6,%7}, {%8,%9}, {%0,%1,%2,%3};\n"
        : "+f"(c[0]), "+f"(c[1]), "+f"(c[2]), "+f"(c[3])
        : "r"(a[0]), "r"(a[1]), "r"(a[2]), "r"(a[3]), "r"(b[0]), "r"(b[1]));
}

__global__ __launch_bounds__(256) void gemm_tf32(
    const float* __restrict__ A, const float* __restrict__ W,
    float* __restrict__ C, int M, int N, int K)
{
    extern __shared__ uint32_t smem_u[];
    uint32_t* SA = smem_u;              // 2 stages of [128][36]
    uint32_t* SB = smem_u + 2 * ASZ;    // 2 stages of [128][36]

    const int tid  = threadIdx.x;
    const int lane = tid & 31;
    const int wid  = tid >> 5;
    const int wm   = (wid & 1) * 64;    // warp M offset in tile
    const int wn   = (wid >> 1) * 32;   // warp N offset in tile
    const int g    = lane >> 2;         // group id (0..7)
    const int t    = lane & 3;          // thread in group (0..3)

    const int bm = blockIdx.y * TBM;
    const int bn = blockIdx.x * TBN;

    // Global load mapping: 4 float4 per thread per operand per stage
    const int r0 = tid >> 3;            // 0..31  (row base, +32*i)
    const int c4 = (tid & 7) * 4;       // 0..28  (col within BK)
    const float* Ag = A + (size_t)(bm + r0) * K + c4;
    const float* Bg = W + (size_t)(bn + r0) * K + c4;

    float acc[4][4][4];
#pragma unroll
    for (int mt = 0; mt < 4; mt++)
#pragma unroll
        for (int nt = 0; nt < 4; nt++)
#pragma unroll
            for (int i = 0; i < 4; i++) acc[mt][nt][i] = 0.f;

    float4 ra[4], rb[4];

    // --- prologue: load + store stage 0
#pragma unroll
    for (int i = 0; i < 4; i++) {
        ra[i] = *(const float4*)(Ag + (size_t)(32 * i) * K);
        rb[i] = *(const float4*)(Bg + (size_t)(32 * i) * K);
    }
#pragma unroll
    for (int i = 0; i < 4; i++) {
        uint32_t* da = SA + (r0 + 32 * i) * TST + c4;
        uint4 va = make_uint4(f2tf32(ra[i].x), f2tf32(ra[i].y),
                              f2tf32(ra[i].z), f2tf32(ra[i].w));
        *(uint4*)da = va;
        uint32_t* db = SB + (r0 + 32 * i) * TST + c4;
        uint4 vb = make_uint4(f2tf32(rb[i].x), f2tf32(rb[i].y),
                              f2tf32(rb[i].z), f2tf32(rb[i].w));
        *(uint4*)db = vb;
    }
    __syncthreads();

    const int nk = K / TBK;             // 32
    for (int kt = 0; kt < nk; kt++) {
        const int cur = kt & 1;

        // issue next-stage global loads early (overlap with compute)
        if (kt + 1 < nk) {
            const int ko = (kt + 1) * TBK;
#pragma unroll
            for (int i = 0; i < 4; i++) {
                ra[i] = *(const float4*)(Ag + (size_t)(32 * i) * K + ko);
                rb[i] = *(const float4*)(Bg + (size_t)(32 * i) * K + ko);
            }
        }

        // compute on current stage
        const uint32_t* as = SA + cur * ASZ + (wm + g) * TST;
        const uint32_t* bs = SB + cur * BSZ + (wn + g) * TST;
#pragma unroll
        for (int ks = 0; ks < 4; ks++) {
            uint32_t af[4][4], bf[4][2];
#pragma unroll
            for (int mt = 0; mt < 4; mt++) {
                const uint32_t* p = as + mt * 16 * TST + ks * 8 + t;
                af[mt][0] = p[0];
                af[mt][1] = p[8 * TST];
                af[mt][2] = p[4];
                af[mt][3] = p[8 * TST + 4];
            }
#pragma unroll
            for (int nt = 0; nt < 4; nt++) {
                const uint32_t* p = bs + nt * 8 * TST + ks * 8 + t;
                bf[nt][0] = p[0];
                bf[nt][1] = p[4];
            }
#pragma unroll
            for (int mt = 0; mt < 4; mt++)
#pragma unroll
                for (int nt = 0; nt < 4; nt++)
                    mma_tf32(acc[mt][nt], af[mt], bf[nt]);
        }
        __syncthreads();

        // store next stage
        if (kt + 1 < nk) {
            const int nxt = cur ^ 1;
#pragma unroll
            for (int i = 0; i < 4; i++) {
                uint32_t* da = SA + nxt * ASZ + (r0 + 32 * i) * TST + c4;
                uint4 va = make_uint4(f2tf32(ra[i].x), f2tf32(ra[i].y),
                                      f2tf32(ra[i].z), f2tf32(ra[i].w));
                *(uint4*)da = va;
                uint32_t* db = SB + nxt * BSZ + (r0 + 32 * i) * TST + c4;
                uint4 vb = make_uint4(f2tf32(rb[i].x), f2tf32(rb[i].y),
                                      f2tf32(rb[i].z), f2tf32(rb[i].w));
                *(uint4*)db = vb;
            }
            __syncthreads();
        }
    }

    // epilogue: c0,c1 -> (row g, cols 2t,2t+1); c2,c3 -> row g+8
    float* Cp = C + (size_t)(bm + wm + g) * N + bn + wn + 2 * t;
#pragma unroll
    for (int mt = 0; mt < 4; mt++) {
#pragma unroll
        for (int nt = 0; nt < 4; nt++) {
            float* p0 = Cp + (size_t)(mt * 16) * N + nt * 8;
            *(float2*)p0 = make_float2(acc[mt][nt][0], acc[mt][nt][1]);
            float* p1 = p0 + (size_t)8 * N;
            *(float2*)p1 = make_float2(acc[mt][nt][2], acc[mt][nt][3]);
        }
    }
}

// ---------------------------------------------------------------------------
// Causal flash attention (unchanged from R1): per (b,h), 64x64 tiles,
// online softmax, 256 threads, 4x4 micro-tiles, causal tile skipping.
// ---------------------------------------------------------------------------
#define AT 64
#define AP (AT + 4)

__global__ __launch_bounds__(256) void attn_kernel(
    const float* __restrict__ Q, const float* __restrict__ K,
    const float* __restrict__ V, float* __restrict__ O)
{
    extern __shared__ float sm[];
    float (*Qs)[AP] = (float (*)[AP])(sm);
    float (*Ks)[AP] = (float (*)[AP])(sm + 64 * AP);
    float (*Vs)[AP] = (float (*)[AP])(sm + 2 * 64 * AP);
    float (*Ps)[AP] = (float (*)[AP])(sm + 3 * 64 * AP);

    const int tid = threadIdx.x;
    const int tr  = tid >> 4;
    const int tc  = tid & 15;
    const int bh  = blockIdx.y;
    const int b   = bh >> 4;
    const int h   = bh & 15;
    const int q0  = blockIdx.x * AT;

    const float* Qp = Q + (size_t)b * S_ * D_ + (size_t)h * DK_;
    const float* Kp = K + (size_t)b * S_ * D_ + (size_t)h * DK_;
    const float* Vp = V + (size_t)b * S_ * D_ + (size_t)h * DK_;
    float*       Op = O + (size_t)b * S_ * D_ + (size_t)h * DK_;

#pragma unroll
    for (int i = 0; i < 4; i++) {
        int idx = tid + i * 256;
        int row = idx >> 4;
        int c4  = (idx & 15) * 4;
        float4 v = *(const float4*)(Qp + (size_t)(q0 + row) * D_ + c4);
        Qs[c4 + 0][row] = v.x; Qs[c4 + 1][row] = v.y;
        Qs[c4 + 2][row] = v.z; Qs[c4 + 3][row] = v.w;
    }

    float acc[4][4];
#pragma unroll
    for (int i = 0; i < 4; i++)
#pragma unroll
        for (int j = 0; j < 4; j++) acc[i][j] = 0.f;
    float mi[4], li[4];
#pragma unroll
    for (int i = 0; i < 4; i++) { mi[i] = -1e30f; li[i] = 0.f; }

    const int last_kt = blockIdx.x;
    const float sc = 0.125f;

    for (int kt = 0; kt <= last_kt; kt++) {
        const int k0 = kt * AT;
        __syncthreads();

#pragma unroll
        for (int i = 0; i < 4; i++) {
            int idx = tid + i * 256;
            int row = idx >> 4;
            int c4  = (idx & 15) * 4;
            float4 vk = *(const float4*)(Kp + (size_t)(k0 + row) * D_ + c4);
            Ks[c4 + 0][row] = vk.x; Ks[c4 + 1][row] = vk.y;
            Ks[c4 + 2][row] = vk.z; Ks[c4 + 3][row] = vk.w;
            float4 vv = *(const float4*)(Vp + (size_t)(k0 + row) * D_ + c4);
            *(float4*)&Vs[row][c4] = vv;
        }
        __syncthreads();

        float s[4][4];
#pragma unroll
        for (int i = 0; i < 4; i++)
#pragma unroll
            for (int j = 0; j < 4; j++) s[i][j] = 0.f;
#pragma unroll
        for (int d = 0; d < DK_; d++) {
            float a[4], bb[4];
            *(float4*)a  = *(const float4*)&Qs[d][tr * 4];
            *(float4*)bb = *(const float4*)&Ks[d][tc * 4];
#pragma unroll
            for (int i = 0; i < 4; i++)
#pragma unroll
                for (int j = 0; j < 4; j++)
                    s[i][j] += a[i] * bb[j];
        }

        if (kt == last_kt) {
#pragma unroll
            for (int i = 0; i < 4; i++) {
                int qg = tr * 4 + i;
#pragma unroll
                for (int j = 0; j < 4; j++) {
                    int kg = tc * 4 + j;
                    s[i][j] = (kg <= qg) ? s[i][j] * sc : -1e30f;
                }
            }
        } else {
#pragma unroll
            for (int i = 0; i < 4; i++)
#pragma unroll
                for (int j = 0; j < 4; j++) s[i][j] *= sc;
        }

#pragma unroll
        for (int i = 0; i < 4; i++) {
            float rm = fmaxf(fmaxf(s[i][0], s[i][1]), fmaxf(s[i][2], s[i][3]));
#pragma unroll
            for (int o = 8; o > 0; o >>= 1)
                rm = fmaxf(rm, __shfl_xor_sync(0xffffffffu, rm, o));
            float mnew = fmaxf(mi[i], rm);
            float p[4], rs = 0.f;
#pragma unroll
            for (int j = 0; j < 4; j++) {
                p[j] = __expf(s[i][j] - mnew);
                rs += p[j];
            }
#pragma unroll
            for (int o = 8; o > 0; o >>= 1)
                rs += __shfl_xor_sync(0xffffffffu, rs, o);
            float alpha = __expf(mi[i] - mnew);
            li[i] = li[i] * alpha + rs;
            mi[i] = mnew;
#pragma unroll
            for (int j = 0; j < 4; j++) acc[i][j] *= alpha;
#pragma unroll
            for (int j = 0; j < 4; j++)
                Ps[tc * 4 + j][tr * 4 + i] = p[j];
        }
        __syncthreads();

#pragma unroll
        for (int kk = 0; kk < AT; kk++) {
            float a[4], bb[4];
            *(float4*)a  = *(const float4*)&Ps[kk][tr * 4];
            *(float4*)bb = *(const float4*)&Vs[kk][tc * 4];
#pragma unroll
            for (int i = 0; i < 4; i++)
#pragma unroll
                for (int j = 0; j < 4; j++)
                    acc[i][j] += a[i] * bb[j];
        }
    }

#pragma unroll
    for (int i = 0; i < 4; i++) {
        float inv = 1.0f / li[i];
        float4 o = make_float4(acc[i][0] * inv, acc[i][1] * inv,
                               acc[i][2] * inv, acc[i][3] * inv);
        *(float4*)(Op + (size_t)(q0 + tr * 4 + i) * D_ + tc * 4) = o;
    }
}

// ---------------------------------------------------------------------------
// Launch
// ---------------------------------------------------------------------------
#define ATTN_SMEM (4 * 64 * AP * (int)sizeof(float))

extern "C" void kernel_launch(void* const* d_in, const int* in_sizes, int n_in,
                              void* d_out, int out_size)
{
    const float* x  = (const float*)d_in[0];
    const float* WQ = (const float*)d_in[1];
    const float* WK = (const float*)d_in[2];
    const float* WV = (const float*)d_in[3];
    const float* WO = (const float*)d_in[4];
    float* out = (float*)d_out;

    float *Qp, *Kp, *Vp, *Ap;
    cudaGetSymbolAddress((void**)&Qp, g_Q);
    cudaGetSymbolAddress((void**)&Kp, g_K);
    cudaGetSymbolAddress((void**)&Vp, g_V);
    cudaGetSymbolAddress((void**)&Ap, g_A);

    cudaFuncSetAttribute(gemm_tf32,
                         cudaFuncAttributeMaxDynamicSharedMemorySize,
                         GEMM_SMEM);
    cudaFuncSetAttribute(attn_kernel,
                         cudaFuncAttributeMaxDynamicSharedMemorySize,
                         ATTN_SMEM);

    const int M = B_ * S_;                 // 8192
    dim3 gg(D_ / TBN, M / TBM);            // (8, 64)

    gemm_tf32<<<gg, 256, GEMM_SMEM>>>(x, WQ, Qp, M, D_, D_);
    gemm_tf32<<<gg, 256, GEMM_SMEM>>>(x, WK, Kp, M, D_, D_);
    gemm_tf32<<<gg, 256, GEMM_SMEM>>>(x, WV, Vp, M, D_, D_);

    attn_kernel<<<dim3(S_ / AT, B_ * H_), 256, ATTN_SMEM>>>(Qp, Kp, Vp, Ap);

    gemm_tf32<<<gg, 256, GEMM_SMEM>>>(Ap, WO, out, M, D_, D_);
}

// round 6
// speedup vs baseline: 1.6897x; 1.0059x over previous
#include <cuda_runtime.h>
#include <math.h>
#include <stdint.h>

#define B_  4
#define S_  2048
#define D_  1024
#define H_  16
#define DK_ 64

// Scratch (allocation-free rule: __device__ globals)
__device__ float g_Q[(size_t)B_ * S_ * D_];
__device__ float g_K[(size_t)B_ * S_ * D_];
__device__ float g_V[(size_t)B_ * S_ * D_];
__device__ float g_A[(size_t)B_ * S_ * D_];
__device__ float g_X[(size_t)B_ * S_ * D_];          // tf32-rounded x
__device__ float g_WR[(size_t)4 * D_ * D_];          // tf32-rounded WQ,WK,WV,WO

__device__ __forceinline__ uint32_t f2tf32(float x) {
    uint32_t r;
    asm("cvt.rna.tf32.f32 %0, %1;" : "=r"(r) : "f"(x));
    return r;
}

// ---------------------------------------------------------------------------
// Elementwise tf32 pre-round (rna), float4 vectorized.
// ---------------------------------------------------------------------------
__global__ void round_tf32_k(const float4* __restrict__ in,
                             float4* __restrict__ out, int n4)
{
    int i = blockIdx.x * blockDim.x + threadIdx.x;
    if (i < n4) {
        float4 v = in[i];
        uint4 u = make_uint4(f2tf32(v.x), f2tf32(v.y), f2tf32(v.z), f2tf32(v.w));
        out[i] = *(float4*)&u;
    }
}

// ---------------------------------------------------------------------------
// TF32 tensor-core GEMM (fastpath, cp.async 3-stage):
// C[M,N] = A[M,K] @ W[N,K]^T, inputs already tf32-rounded.
// Block 128x128x32, 256 threads, warp tile 64x32, smem stride 36 (no conflicts).
// ---------------------------------------------------------------------------
#define TBM 128
#define TBN 128
#define TBK 32
#define TST 36
#define ASZ (TBM * TST)
#define BSZ (TBN * TST)
#define NSTG 3
#define GEMM_SMEM (NSTG * (ASZ + BSZ) * 4)    // 110592 B

__device__ __forceinline__ void cp16(uint32_t dst_smem, const void* src) {
    asm volatile("cp.async.cg.shared.global [%0], [%1], 16;\n"
                 :: "r"(dst_smem), "l"(src));
}

__device__ __forceinline__ void mma_tf32(float c[4], const uint32_t a[4],
                                         const uint32_t b[2]) {
    asm volatile(
        "mma.sync.aligned.m16n8k8.row.col.f32.tf32.tf32.f32 "
        "{%0,%1,%2,%3}, {%4,%5,%6,%7}, {%8,%9}, {%0,%1,%2,%3};\n"
        : "+f"(c[0]), "+f"(c[1]), "+f"(c[2]), "+f"(c[3])
        : "r"(a[0]), "r"(a[1]), "r"(a[2]), "r"(a[3]), "r"(b[0]), "r"(b[1]));
}

__global__ __launch_bounds__(256) void gemm_tf32(
    const float* __restrict__ A, const float* __restrict__ W,
    float* __restrict__ C, int M, int N, int K)
{
    extern __shared__ uint32_t smem_u[];
    uint32_t* SA = smem_u;                 // NSTG stages of [128][36]
    uint32_t* SB = smem_u + NSTG * ASZ;

    const int tid  = threadIdx.x;
    const int lane = tid & 31;
    const int wid  = tid >> 5;
    const int wm   = (wid & 1) * 64;
    const int wn   = (wid >> 1) * 32;
    const int g    = lane >> 2;
    const int t    = lane & 3;

    const int bm = blockIdx.y * TBM;
    const int bn = blockIdx.x * TBN;

    const int r0 = tid >> 3;               // 0..31 (+32*i)
    const int c4 = (tid & 7) * 4;          // 0..28
    const float* Ag = A + (size_t)(bm + r0) * K + c4;
    const float* Bg = W + (size_t)(bn + r0) * K + c4;

    const uint32_t sa_base = (uint32_t)__cvta_generic_to_shared(SA);
    const uint32_t sb_base = (uint32_t)__cvta_generic_to_shared(SB);

    float acc[4][4][4];
#pragma unroll
    for (int mt = 0; mt < 4; mt++)
#pragma unroll
        for (int nt = 0; nt < 4; nt++)
#pragma unroll
            for (int i = 0; i < 4; i++) acc[mt][nt][i] = 0.f;

    const int nk = K / TBK;

    // prologue: stages 0,1
#pragma unroll
    for (int s = 0; s < 2; s++) {
        const int ko = s * TBK;
#pragma unroll
        for (int i = 0; i < 4; i++) {
            uint32_t da = sa_base + (s * ASZ + (r0 + 32 * i) * TST + c4) * 4;
            cp16(da, Ag + (size_t)(32 * i) * K + ko);
            uint32_t db = sb_base + (s * BSZ + (r0 + 32 * i) * TST + c4) * 4;
            cp16(db, Bg + (size_t)(32 * i) * K + ko);
        }
        asm volatile("cp.async.commit_group;\n");
    }

    int cur = 0;
    for (int kt = 0; kt < nk; kt++) {
        __syncthreads();   // everyone done reading buf about to be refilled
        if (kt + 2 < nk) {
            const int s  = (kt + 2) % NSTG;
            const int ko = (kt + 2) * TBK;
#pragma unroll
            for (int i = 0; i < 4; i++) {
                uint32_t da = sa_base + (s * ASZ + (r0 + 32 * i) * TST + c4) * 4;
                cp16(da, Ag + (size_t)(32 * i) * K + ko);
                uint32_t db = sb_base + (s * BSZ + (r0 + 32 * i) * TST + c4) * 4;
                cp16(db, Bg + (size_t)(32 * i) * K + ko);
            }
        }
        asm volatile("cp.async.commit_group;\n");
        asm volatile("cp.async.wait_group 2;\n");
        __syncthreads();   // make stage kt visible to all threads

        const uint32_t* as = SA + cur * ASZ + (wm + g) * TST;
        const uint32_t* bs = SB + cur * BSZ + (wn + g) * TST;
#pragma unroll
        for (int ks = 0; ks < 4; ks++) {
            uint32_t af[4][4], bf[4][2];
#pragma unroll
            for (int mt = 0; mt < 4; mt++) {
                const uint32_t* p = as + mt * 16 * TST + ks * 8 + t;
                af[mt][0] = p[0];
                af[mt][1] = p[8 * TST];
                af[mt][2] = p[4];
                af[mt][3] = p[8 * TST + 4];
            }
#pragma unroll
            for (int nt = 0; nt < 4; nt++) {
                const uint32_t* p = bs + nt * 8 * TST + ks * 8 + t;
                bf[nt][0] = p[0];
                bf[nt][1] = p[4];
            }
#pragma unroll
            for (int mt = 0; mt < 4; mt++)
#pragma unroll
                for (int nt = 0; nt < 4; nt++)
                    mma_tf32(acc[mt][nt], af[mt], bf[nt]);
        }
        cur = (cur + 1) % NSTG;
    }

    // epilogue
    float* Cp = C + (size_t)(bm + wm + g) * N + bn + wn + 2 * t;
#pragma unroll
    for (int mt = 0; mt < 4; mt++) {
#pragma unroll
        for (int nt = 0; nt < 4; nt++) {
            float* p0 = Cp + (size_t)(mt * 16) * N + nt * 8;
            *(float2*)p0 = make_float2(acc[mt][nt][0], acc[mt][nt][1]);
            float* p1 = p0 + (size_t)8 * N;
            *(float2*)p1 = make_float2(acc[mt][nt][2], acc[mt][nt][3]);
        }
    }
}

// ---------------------------------------------------------------------------
// Causal flash attention: 128q x 64k tiles, 256 threads, 8x4 micro-tiles
// (rebalances LDS:FFMA from 2:1 to 1.5:1). Heavy tiles launched first.
// ---------------------------------------------------------------------------
#define AQ  128
#define AKT 64
#define AQP 132
#define AKP 68
#define ATTN_SMEM ((64 * AQP + 64 * AKP + 64 * AKP + 64 * AQP) * 4)  // 102400

__global__ __launch_bounds__(256) void attn_kernel(
    const float* __restrict__ Q, const float* __restrict__ K,
    const float* __restrict__ V, float* __restrict__ O)
{
    extern __shared__ float sm[];
    float (*Qs)[AQP] = (float (*)[AQP])(sm);                         // [d][q]
    float (*Ks)[AKP] = (float (*)[AKP])(sm + 64 * AQP);              // [d][k]
    float (*Vs)[AKP] = (float (*)[AKP])(sm + 64 * AQP + 64 * AKP);   // [k][d]
    float (*Ps)[AQP] = (float (*)[AQP])(sm + 64 * AQP + 2 * 64 * AKP); // [k][q]

    const int tid = threadIdx.x;
    const int tr  = tid >> 4;     // q group 0..15 (8 rows each)
    const int tc  = tid & 15;     // k/d group 0..15 (4 cols each)
    const int bh  = blockIdx.y;
    const int b   = bh >> 4;
    const int h   = bh & 15;
    const int qm  = gridDim.x - 1 - blockIdx.x;   // heavy tiles first
    const int q0  = qm * AQ;

    const float* Qp = Q + (size_t)b * S_ * D_ + (size_t)h * DK_;
    const float* Kp = K + (size_t)b * S_ * D_ + (size_t)h * DK_;
    const float* Vp = V + (size_t)b * S_ * D_ + (size_t)h * DK_;
    float*       Op = O + (size_t)b * S_ * D_ + (size_t)h * DK_;

    // Load Q tile (128 x 64) transposed to [d][q]
#pragma unroll
    for (int i = 0; i < 8; i++) {
        int idx = tid + i * 256;          // 0..2047
        int row = idx >> 4;               // 0..127
        int c4  = (idx & 15) * 4;         // 0..60
        float4 v = *(const float4*)(Qp + (size_t)(q0 + row) * D_ + c4);
        Qs[c4 + 0][row] = v.x; Qs[c4 + 1][row] = v.y;
        Qs[c4 + 2][row] = v.z; Qs[c4 + 3][row] = v.w;
    }

    float acc[8][4];
#pragma unroll
    for (int i = 0; i < 8; i++)
#pragma unroll
        for (int j = 0; j < 4; j++) acc[i][j] = 0.f;
    float mi[8], li[8];
#pragma unroll
    for (int i = 0; i < 8; i++) { mi[i] = -1e30f; li[i] = 0.f; }

    const int last_kt = q0 / 64 + 1;      // k-tiles 0..last_kt cover q0+127
    const float sc = 0.125f;

    for (int kt = 0; kt <= last_kt; kt++) {
        const int k0 = kt * AKT;
        __syncthreads();

        // Load K transposed [d][k], V natural [k][d]  (64x64 each)
#pragma unroll
        for (int i = 0; i < 4; i++) {
            int idx = tid + i * 256;
            int row = idx >> 4;           // 0..63
            int c4  = (idx & 15) * 4;
            float4 vk = *(const float4*)(Kp + (size_t)(k0 + row) * D_ + c4);
            Ks[c4 + 0][row] = vk.x; Ks[c4 + 1][row] = vk.y;
            Ks[c4 + 2][row] = vk.z; Ks[c4 + 3][row] = vk.w;
            float4 vv = *(const float4*)(Vp + (size_t)(k0 + row) * D_ + c4);
            *(float4*)&Vs[row][c4] = vv;
        }
        __syncthreads();

        // S = Q @ K^T
        float s[8][4];
#pragma unroll
        for (int i = 0; i < 8; i++)
#pragma unroll
            for (int j = 0; j < 4; j++) s[i][j] = 0.f;
#pragma unroll
        for (int d = 0; d < DK_; d++) {
            float a[8], bb[4];
            *(float4*)(a)     = *(const float4*)&Qs[d][tr * 8];
            *(float4*)(a + 4) = *(const float4*)&Qs[d][tr * 8 + 4];
            *(float4*)bb      = *(const float4*)&Ks[d][tc * 4];
#pragma unroll
            for (int i = 0; i < 8; i++)
#pragma unroll
                for (int j = 0; j < 4; j++)
                    s[i][j] += a[i] * bb[j];
        }

        // Scale + causal mask (only tiles with k0 >= q0 need masking)
        if (k0 >= q0) {
#pragma unroll
            for (int i = 0; i < 8; i++) {
                int qg = q0 + tr * 8 + i;
#pragma unroll
                for (int j = 0; j < 4; j++) {
                    int kg = k0 + tc * 4 + j;
                    s[i][j] = (kg <= qg) ? s[i][j] * sc : -1e30f;
                }
            }
        } else {
#pragma unroll
            for (int i = 0; i < 8; i++)
#pragma unroll
                for (int j = 0; j < 4; j++) s[i][j] *= sc;
        }

        // Online softmax (row spans 16 tc lanes; xor<=8 stays in-group)
#pragma unroll
        for (int i = 0; i < 8; i++) {
            float rm = fmaxf(fmaxf(s[i][0], s[i][1]), fmaxf(s[i][2], s[i][3]));
#pragma unroll
            for (int o = 8; o > 0; o >>= 1)
                rm = fmaxf(rm, __shfl_xor_sync(0xffffffffu, rm, o));
            float mnew = fmaxf(mi[i], rm);
            float p[4], rs = 0.f;
#pragma unroll
            for (int j = 0; j < 4; j++) {
                p[j] = __expf(s[i][j] - mnew);
                rs += p[j];
            }
#pragma unroll
            for (int o = 8; o > 0; o >>= 1)
                rs += __shfl_xor_sync(0xffffffffu, rs, o);
            float alpha = __expf(mi[i] - mnew);
            li[i] = li[i] * alpha + rs;
            mi[i] = mnew;
#pragma unroll
            for (int j = 0; j < 4; j++) acc[i][j] *= alpha;
#pragma unroll
            for (int j = 0; j < 4; j++)
                Ps[tc * 4 + j][tr * 8 + i] = p[j];
        }
        __syncthreads();

        // O += P @ V
#pragma unroll
        for (int kk = 0; kk < AKT; kk++) {
            float a[8], bb[4];
            *(float4*)(a)     = *(const float4*)&Ps[kk][tr * 8];
            *(float4*)(a + 4) = *(const float4*)&Ps[kk][tr * 8 + 4];
            *(float4*)bb      = *(const float4*)&Vs[kk][tc * 4];
#pragma unroll
            for (int i = 0; i < 8; i++)
#pragma unroll
                for (int j = 0; j < 4; j++)
                    acc[i][j] += a[i] * bb[j];
        }
    }

    // Epilogue
#pragma unroll
    for (int i = 0; i < 8; i++) {
        float inv = 1.0f / li[i];
        float4 o = make_float4(acc[i][0] * inv, acc[i][1] * inv,
                               acc[i][2] * inv, acc[i][3] * inv);
        *(float4*)(Op + (size_t)(q0 + tr * 8 + i) * D_ + tc * 4) = o;
    }
}

// ---------------------------------------------------------------------------
// Launch
// ---------------------------------------------------------------------------
extern "C" void kernel_launch(void* const* d_in, const int* in_sizes, int n_in,
                              void* d_out, int out_size)
{
    const float* x  = (const float*)d_in[0];
    const float* WQ = (const float*)d_in[1];
    const float* WK = (const float*)d_in[2];
    const float* WV = (const float*)d_in[3];
    const float* WO = (const float*)d_in[4];
    float* out = (float*)d_out;

    float *Qp, *Kp, *Vp, *Ap, *Xp, *Wr;
    cudaGetSymbolAddress((void**)&Qp, g_Q);
    cudaGetSymbolAddress((void**)&Kp, g_K);
    cudaGetSymbolAddress((void**)&Vp, g_V);
    cudaGetSymbolAddress((void**)&Ap, g_A);
    cudaGetSymbolAddress((void**)&Xp, g_X);
    cudaGetSymbolAddress((void**)&Wr, g_WR);

    cudaFuncSetAttribute(gemm_tf32,
                         cudaFuncAttributeMaxDynamicSharedMemorySize,
                         GEMM_SMEM);
    cudaFuncSetAttribute(attn_kernel,
                         cudaFuncAttributeMaxDynamicSharedMemorySize,
                         ATTN_SMEM);

    const int M  = B_ * S_;                        // 8192
    const int nX4 = (M * D_) / 4;                  // 2,097,152
    const int nW4 = (D_ * D_) / 4;                 // 262,144

    // Pre-round inputs to tf32 (rna) — fastpath
    round_tf32_k<<<(nX4 + 255) / 256, 256>>>((const float4*)x, (float4*)Xp, nX4);
    round_tf32_k<<<(nW4 + 255) / 256, 256>>>((const float4*)WQ, (float4*)(Wr + 0 * (size_t)D_ * D_), nW4);
    round_tf32_k<<<(nW4 + 255) / 256, 256>>>((const float4*)WK, (float4*)(Wr + 1 * (size_t)D_ * D_), nW4);
    round_tf32_k<<<(nW4 + 255) / 256, 256>>>((const float4*)WV, (float4*)(Wr + 2 * (size_t)D_ * D_), nW4);
    round_tf32_k<<<(nW4 + 255) / 256, 256>>>((const float4*)WO, (float4*)(Wr + 3 * (size_t)D_ * D_), nW4);

    dim3 gg(D_ / TBN, M / TBM);                    // (8, 64)
    gemm_tf32<<<gg, 256, GEMM_SMEM>>>(Xp, Wr + 0 * (size_t)D_ * D_, Qp, M, D_, D_);
    gemm_tf32<<<gg, 256, GEMM_SMEM>>>(Xp, Wr + 1 * (size_t)D_ * D_, Kp, M, D_, D_);
    gemm_tf32<<<gg, 256, GEMM_SMEM>>>(Xp, Wr + 2 * (size_t)D_ * D_, Vp, M, D_, D_);

    attn_kernel<<<dim3(S_ / AQ, B_ * H_), 256, ATTN_SMEM>>>(Qp, Kp, Vp, Ap);

    // Round attention output in-place, then final projection
    round_tf32_k<<<(nX4 + 255) / 256, 256>>>((const float4*)Ap, (float4*)Ap, nX4);
    gemm_tf32<<<gg, 256, GEMM_SMEM>>>(Ap, Wr + 3 * (size_t)D_ * D_, out, M, D_, D_);
}

// round 8
// speedup vs baseline: 1.9156x; 1.1337x over previous
#include <cuda_runtime.h>
#include <cuda_fp16.h>
#include <math.h>
#include <stdint.h>

#define B_  4
#define S_  2048
#define D_  1024
#define H_  16
#define DK_ 64

// Scratch (allocation-free rule: __device__ globals)
__device__ float  g_Q[(size_t)B_ * S_ * D_];
__device__ float  g_K[(size_t)B_ * S_ * D_];
__device__ float  g_V[(size_t)B_ * S_ * D_];
__device__ float  g_A[(size_t)B_ * S_ * D_];
__device__ __half g_Xh[(size_t)B_ * S_ * D_];        // fp16 x
__device__ __half g_Wh[(size_t)4 * D_ * D_];         // fp16 WQ,WK,WV,WO
__device__ __half g_Ah[(size_t)B_ * S_ * D_];        // fp16 attention out

// ---------------------------------------------------------------------------
// fp32 -> fp16 convert, 8 elems/thread.
// ---------------------------------------------------------------------------
__global__ void cvt_f16_k(const float4* __restrict__ in,
                          uint4* __restrict__ out, int n8)
{
    int i = blockIdx.x * blockDim.x + threadIdx.x;
    if (i < n8) {
        float4 a = in[2 * i];
        float4 b = in[2 * i + 1];
        __half2 h0 = __floats2half2_rn(a.x, a.y);
        __half2 h1 = __floats2half2_rn(a.z, a.w);
        __half2 h2 = __floats2half2_rn(b.x, b.y);
        __half2 h3 = __floats2half2_rn(b.z, b.w);
        uint4 u;
        u.x = *(uint32_t*)&h0; u.y = *(uint32_t*)&h1;
        u.z = *(uint32_t*)&h2; u.w = *(uint32_t*)&h3;
        out[i] = u;
    }
}

// ---------------------------------------------------------------------------
// FP16 tensor-core GEMM: C[M,N] = A[M,K] @ W[N,K]^T (fp16 in, fp32 out)
// Block 128x128x32(halves), 256 threads, warp tile 64x32, m16n8k16.
// Smem row stride 40 halves (80B): conflict-free fragment loads, 16B aligned.
// 4-stage cp.async pipeline.
// ---------------------------------------------------------------------------
#define TBM 128
#define TBN 128
#define TBK 32
#define TSTH 40
#define ASZH (TBM * TSTH)              // halves per A stage (5120)
#define BSZH (TBN * TSTH)
#define NSTG 4
#define GEMM_SMEM (NSTG * (ASZH + BSZH) * 2)   // 81920 B

__device__ __forceinline__ void cp16(uint32_t dst_smem, const void* src) {
    asm volatile("cp.async.cg.shared.global [%0], [%1], 16;\n"
                 :: "r"(dst_smem), "l"(src));
}

__device__ __forceinline__ void mma_f16(float c[4], const uint32_t a[4],
                                        const uint32_t b[2]) {
    asm volatile(
        "mma.sync.aligned.m16n8k16.row.col.f32.f16.f16.f32 "
        "{%0,%1,%2,%3}, {%4,%5,%6,%7}, {%8,%9}, {%0,%1,%2,%3};\n"
        : "+f"(c[0]), "+f"(c[1]), "+f"(c[2]), "+f"(c[3])
        : "r"(a[0]), "r"(a[1]), "r"(a[2]), "r"(a[3]), "r"(b[0]), "r"(b[1]));
}

__global__ __launch_bounds__(256) void gemm_f16(
    const __half* __restrict__ A, const __half* __restrict__ W,
    float* __restrict__ C, int M, int N, int K)
{
    extern __shared__ __half smem_h[];
    __half* SA = smem_h;                    // NSTG stages of [128][40]
    __half* SB = smem_h + NSTG * ASZH;

    const int tid  = threadIdx.x;
    const int lane = tid & 31;
    const int wid  = tid >> 5;
    const int wm   = (wid & 1) * 64;
    const int wn   = (wid >> 1) * 32;
    const int g    = lane >> 2;
    const int t    = lane & 3;

    const int bm = blockIdx.y * TBM;
    const int bn = blockIdx.x * TBN;

    const uint32_t sa_base = (uint32_t)__cvta_generic_to_shared(SA);
    const uint32_t sb_base = (uint32_t)__cvta_generic_to_shared(SB);

    // Global->smem mapping: idx = tid + 256*i covers (row, 16B-unit)
    const int r0 = tid >> 2;                // 0..63 (+64*i)
    const int u0 = (tid & 3) * 8;           // half offset of 16B unit

    float acc[4][4][4];
#pragma unroll
    for (int mt = 0; mt < 4; mt++)
#pragma unroll
        for (int nt = 0; nt < 4; nt++)
#pragma unroll
            for (int i = 0; i < 4; i++) acc[mt][nt][i] = 0.f;

    const int nk = K / TBK;                 // 32

    auto load_stage = [&](int kt) {
        const int s  = kt % NSTG;
        const int ke = kt * TBK;
#pragma unroll
        for (int i = 0; i < 2; i++) {       // A: 128 rows x 4 units
            int row = r0 + 64 * i;
            uint32_t dst = sa_base + (s * ASZH + row * TSTH + u0) * 2;
            cp16(dst, A + (size_t)(bm + row) * K + ke + u0);
        }
#pragma unroll
        for (int i = 0; i < 2; i++) {       // B: 128 rows x 4 units
            int row = r0 + 64 * i;
            uint32_t dst = sb_base + (s * BSZH + row * TSTH + u0) * 2;
            cp16(dst, W + (size_t)(bn + row) * K + ke + u0);
        }
    };

    // prologue: stages 0..2
#pragma unroll
    for (int s = 0; s < NSTG - 1; s++) {
        load_stage(s);
        asm volatile("cp.async.commit_group;\n");
    }

    for (int kt = 0; kt < nk; kt++) {
        if (kt + NSTG - 1 < nk) load_stage(kt + NSTG - 1);
        asm volatile("cp.async.commit_group;\n");
        asm volatile("cp.async.wait_group %0;\n" :: "n"(NSTG - 1));
        __syncthreads();

        const int s = kt % NSTG;
        const __half* as = SA + s * ASZH + (wm + g) * TSTH;
        const __half* bs = SB + s * BSZH + (wn + g) * TSTH;
#pragma unroll
        for (int ks = 0; ks < 2; ks++) {
            const int cb = ks * 16;
            uint32_t af[4][4], bf[4][2];
#pragma unroll
            for (int mt = 0; mt < 4; mt++) {
                const __half* p = as + mt * 16 * TSTH + cb + 2 * t;
                af[mt][0] = *(const uint32_t*)(p);
                af[mt][1] = *(const uint32_t*)(p + 8 * TSTH);
                af[mt][2] = *(const uint32_t*)(p + 8);
                af[mt][3] = *(const uint32_t*)(p + 8 * TSTH + 8);
            }
#pragma unroll
            for (int nt = 0; nt < 4; nt++) {
                const __half* p = bs + nt * 8 * TSTH + cb + 2 * t;
                bf[nt][0] = *(const uint32_t*)(p);
                bf[nt][1] = *(const uint32_t*)(p + 8);
            }
#pragma unroll
            for (int mt = 0; mt < 4; mt++)
#pragma unroll
                for (int nt = 0; nt < 4; nt++)
                    mma_f16(acc[mt][nt], af[mt], bf[nt]);
        }
        __syncthreads();
    }

    // epilogue: c0,c1 -> (row g, cols 2t,2t+1); c2,c3 -> row g+8
    float* Cp = C + (size_t)(bm + wm + g) * N + bn + wn + 2 * t;
#pragma unroll
    for (int mt = 0; mt < 4; mt++) {
#pragma unroll
        for (int nt = 0; nt < 4; nt++) {
            float* p0 = Cp + (size_t)(mt * 16) * N + nt * 8;
            *(float2*)p0 = make_float2(acc[mt][nt][0], acc[mt][nt][1]);
            float* p1 = p0 + (size_t)8 * N;
            *(float2*)p1 = make_float2(acc[mt][nt][2], acc[mt][nt][3]);
        }
    }
}

// ---------------------------------------------------------------------------
// Causal flash attention (unchanged, known-good): 128q x 64k tiles,
// 256 threads, 8x4 micro-tiles, heavy tiles first.
// ---------------------------------------------------------------------------
#define AQ  128
#define AKT 64
#define AQP 132
#define AKP 68
#define ATTN_SMEM ((64 * AQP + 64 * AKP + 64 * AKP + 64 * AQP) * 4)

__global__ __launch_bounds__(256) void attn_kernel(
    const float* __restrict__ Q, const float* __restrict__ K,
    const float* __restrict__ V, float* __restrict__ O)
{
    extern __shared__ float sm[];
    float (*Qs)[AQP] = (float (*)[AQP])(sm);
    float (*Ks)[AKP] = (float (*)[AKP])(sm + 64 * AQP);
    float (*Vs)[AKP] = (float (*)[AKP])(sm + 64 * AQP + 64 * AKP);
    float (*Ps)[AQP] = (float (*)[AQP])(sm + 64 * AQP + 2 * 64 * AKP);

    const int tid = threadIdx.x;
    const int tr  = tid >> 4;
    const int tc  = tid & 15;
    const int bh  = blockIdx.y;
    const int b   = bh >> 4;
    const int h   = bh & 15;
    const int qm  = gridDim.x - 1 - blockIdx.x;
    const int q0  = qm * AQ;

    const float* Qp = Q + (size_t)b * S_ * D_ + (size_t)h * DK_;
    const float* Kp = K + (size_t)b * S_ * D_ + (size_t)h * DK_;
    const float* Vp = V + (size_t)b * S_ * D_ + (size_t)h * DK_;
    float*       Op = O + (size_t)b * S_ * D_ + (size_t)h * DK_;

#pragma unroll
    for (int i = 0; i < 8; i++) {
        int idx = tid + i * 256;
        int row = idx >> 4;
        int c4  = (idx & 15) * 4;
        float4 v = *(const float4*)(Qp + (size_t)(q0 + row) * D_ + c4);
        Qs[c4 + 0][row] = v.x; Qs[c4 + 1][row] = v.y;
        Qs[c4 + 2][row] = v.z; Qs[c4 + 3][row] = v.w;
    }

    float acc[8][4];
#pragma unroll
    for (int i = 0; i < 8; i++)
#pragma unroll
        for (int j = 0; j < 4; j++) acc[i][j] = 0.f;
    float mi[8], li[8];
#pragma unroll
    for (int i = 0; i < 8; i++) { mi[i] = -1e30f; li[i] = 0.f; }

    const int last_kt = q0 / 64 + 1;
    const float sc = 0.125f;

    for (int kt = 0; kt <= last_kt; kt++) {
        const int k0 = kt * AKT;
        __syncthreads();

#pragma unroll
        for (int i = 0; i < 4; i++) {
            int idx = tid + i * 256;
            int row = idx >> 4;
            int c4  = (idx & 15) * 4;
            float4 vk = *(const float4*)(Kp + (size_t)(k0 + row) * D_ + c4);
            Ks[c4 + 0][row] = vk.x; Ks[c4 + 1][row] = vk.y;
            Ks[c4 + 2][row] = vk.z; Ks[c4 + 3][row] = vk.w;
            float4 vv = *(const float4*)(Vp + (size_t)(k0 + row) * D_ + c4);
            *(float4*)&Vs[row][c4] = vv;
        }
        __syncthreads();

        float s[8][4];
#pragma unroll
        for (int i = 0; i < 8; i++)
#pragma unroll
            for (int j = 0; j < 4; j++) s[i][j] = 0.f;
#pragma unroll
        for (int d = 0; d < DK_; d++) {
            float a[8], bb[4];
            *(float4*)(a)     = *(const float4*)&Qs[d][tr * 8];
            *(float4*)(a + 4) = *(const float4*)&Qs[d][tr * 8 + 4];
            *(float4*)bb      = *(const float4*)&Ks[d][tc * 4];
#pragma unroll
            for (int i = 0; i < 8; i++)
#pragma unroll
                for (int j = 0; j < 4; j++)
                    s[i][j] += a[i] * bb[j];
        }

        if (k0 >= q0) {
#pragma unroll
            for (int i = 0; i < 8; i++) {
                int qg = q0 + tr * 8 + i;
#pragma unroll
                for (int j = 0; j < 4; j++) {
                    int kg = k0 + tc * 4 + j;
                    s[i][j] = (kg <= qg) ? s[i][j] * sc : -1e30f;
                }
            }
        } else {
#pragma unroll
            for (int i = 0; i < 8; i++)
#pragma unroll
                for (int j = 0; j < 4; j++) s[i][j] *= sc;
        }

#pragma unroll
        for (int i = 0; i < 8; i++) {
            float rm = fmaxf(fmaxf(s[i][0], s[i][1]), fmaxf(s[i][2], s[i][3]));
#pragma unroll
            for (int o = 8; o > 0; o >>= 1)
                rm = fmaxf(rm, __shfl_xor_sync(0xffffffffu, rm, o));
            float mnew = fmaxf(mi[i], rm);
            float p[4], rs = 0.f;
#pragma unroll
            for (int j = 0; j < 4; j++) {
                p[j] = __expf(s[i][j] - mnew);
                rs += p[j];
            }
#pragma unroll
            for (int o = 8; o > 0; o >>= 1)
                rs += __shfl_xor_sync(0xffffffffu, rs, o);
            float alpha = __expf(mi[i] - mnew);
            li[i] = li[i] * alpha + rs;
            mi[i] = mnew;
#pragma unroll
            for (int j = 0; j < 4; j++) acc[i][j] *= alpha;
#pragma unroll
            for (int j = 0; j < 4; j++)
                Ps[tc * 4 + j][tr * 8 + i] = p[j];
        }
        __syncthreads();

#pragma unroll
        for (int kk = 0; kk < AKT; kk++) {
            float a[8], bb[4];
            *(float4*)(a)     = *(const float4*)&Ps[kk][tr * 8];
            *(float4*)(a + 4) = *(const float4*)&Ps[kk][tr * 8 + 4];
            *(float4*)bb      = *(const float4*)&Vs[kk][tc * 4];
#pragma unroll
            for (int i = 0; i < 8; i++)
#pragma unroll
                for (int j = 0; j < 4; j++)
                    acc[i][j] += a[i] * bb[j];
        }
    }

#pragma unroll
    for (int i = 0; i < 8; i++) {
        float inv = 1.0f / li[i];
        float4 o = make_float4(acc[i][0] * inv, acc[i][1] * inv,
                               acc[i][2] * inv, acc[i][3] * inv);
        *(float4*)(Op + (size_t)(q0 + tr * 8 + i) * D_ + tc * 4) = o;
    }
}

// ---------------------------------------------------------------------------
// Launch
// ---------------------------------------------------------------------------
extern "C" void kernel_launch(void* const* d_in, const int* in_sizes, int n_in,
                              void* d_out, int out_size)
{
    const float* x  = (const float*)d_in[0];
    const float* WQ = (const float*)d_in[1];
    const float* WK = (const float*)d_in[2];
    const float* WV = (const float*)d_in[3];
    const float* WO = (const float*)d_in[4];
    float* out = (float*)d_out;

    float *Qp, *Kp, *Vp, *Ap;
    __half *Xh, *Wh, *Ah;
    cudaGetSymbolAddress((void**)&Qp, g_Q);
    cudaGetSymbolAddress((void**)&Kp, g_K);
    cudaGetSymbolAddress((void**)&Vp, g_V);
    cudaGetSymbolAddress((void**)&Ap, g_A);
    cudaGetSymbolAddress((void**)&Xh, g_Xh);
    cudaGetSymbolAddress((void**)&Wh, g_Wh);
    cudaGetSymbolAddress((void**)&Ah, g_Ah);

    cudaFuncSetAttribute(gemm_f16,
                         cudaFuncAttributeMaxDynamicSharedMemorySize,
                         GEMM_SMEM);
    cudaFuncSetAttribute(attn_kernel,
                         cudaFuncAttributeMaxDynamicSharedMemorySize,
                         ATTN_SMEM);

    const int M   = B_ * S_;                       // 8192
    const int nX8 = (M * D_) / 8;                  // 1,048,576
    const int nW8 = (D_ * D_) / 8;                 // 131,072

    // Convert inputs to fp16
    cvt_f16_k<<<(nX8 + 255) / 256, 256>>>((const float4*)x, (uint4*)Xh, nX8);
    cvt_f16_k<<<(nW8 + 255) / 256, 256>>>((const float4*)WQ, (uint4*)(Wh + 0 * (size_t)D_ * D_), nW8);
    cvt_f16_k<<<(nW8 + 255) / 256, 256>>>((const float4*)WK, (uint4*)(Wh + 1 * (size_t)D_ * D_), nW8);
    cvt_f16_k<<<(nW8 + 255) / 256, 256>>>((const float4*)WV, (uint4*)(Wh + 2 * (size_t)D_ * D_), nW8);
    cvt_f16_k<<<(nW8 + 255) / 256, 256>>>((const float4*)WO, (uint4*)(Wh + 3 * (size_t)D_ * D_), nW8);

    dim3 gg(D_ / TBN, M / TBM);                    // (8, 64)
    gemm_f16<<<gg, 256, GEMM_SMEM>>>(Xh, Wh + 0 * (size_t)D_ * D_, Qp, M, D_, D_);
    gemm_f16<<<gg, 256, GEMM_SMEM>>>(Xh, Wh + 1 * (size_t)D_ * D_, Kp, M, D_, D_);
    gemm_f16<<<gg, 256, GEMM_SMEM>>>(Xh, Wh + 2 * (size_t)D_ * D_, Vp, M, D_, D_);

    attn_kernel<<<dim3(S_ / AQ, B_ * H_), 256, ATTN_SMEM>>>(Qp, Kp, Vp, Ap);

    cvt_f16_k<<<(nX8 + 255) / 256, 256>>>((const float4*)Ap, (uint4*)Ah, nX8);
    gemm_f16<<<gg, 256, GEMM_SMEM>>>(Ah, Wh + 3 * (size_t)D_ * D_, out, M, D_, D_);
}

// round 13
// speedup vs baseline: 5.7269x; 2.9896x over previous
#include <cuda_runtime.h>
#include <cuda_fp16.h>
#include <math.h>
#include <stdint.h>

#define B_  4
#define S_  2048
#define D_  1024
#define H_  16
#define DK_ 64

// fp16 scratch (allocation-free rule: __device__ globals)
__device__ __half g_Xh[(size_t)B_ * S_ * D_];
__device__ __half g_Wh[(size_t)4 * D_ * D_];
__device__ __half g_Qh[(size_t)B_ * S_ * D_];
__device__ __half g_Kh[(size_t)B_ * S_ * D_];
__device__ __half g_Vh[(size_t)B_ * S_ * D_];
__device__ __half g_Ah[(size_t)B_ * S_ * D_];

// ---------------------------------------------------------------------------
// fp32 -> fp16 convert, 8 elems/thread.
// ---------------------------------------------------------------------------
__global__ void cvt_f16_k(const float4* __restrict__ in,
                          uint4* __restrict__ out, int n8)
{
    int i = blockIdx.x * blockDim.x + threadIdx.x;
    if (i < n8) {
        float4 a = in[2 * i];
        float4 b = in[2 * i + 1];
        __half2 h0 = __floats2half2_rn(a.x, a.y);
        __half2 h1 = __floats2half2_rn(a.z, a.w);
        __half2 h2 = __floats2half2_rn(b.x, b.y);
        __half2 h3 = __floats2half2_rn(b.z, b.w);
        uint4 u;
        u.x = *(uint32_t*)&h0; u.y = *(uint32_t*)&h1;
        u.z = *(uint32_t*)&h2; u.w = *(uint32_t*)&h3;
        out[i] = u;
    }
}

// ---------------------------------------------------------------------------
// mma / ldmatrix helpers
// ---------------------------------------------------------------------------
__device__ __forceinline__ void cp16(uint32_t dst_smem, const void* src) {
    asm volatile("cp.async.cg.shared.global [%0], [%1], 16;\n"
                 :: "r"(dst_smem), "l"(src));
}

__device__ __forceinline__ void mma_f16(float c[4], const uint32_t a[4],
                                        uint32_t b0, uint32_t b1) {
    asm volatile(
        "mma.sync.aligned.m16n8k16.row.col.f32.f16.f16.f32 "
        "{%0,%1,%2,%3}, {%4,%5,%6,%7}, {%8,%9}, {%0,%1,%2,%3};\n"
        : "+f"(c[0]), "+f"(c[1]), "+f"(c[2]), "+f"(c[3])
        : "r"(a[0]), "r"(a[1]), "r"(a[2]), "r"(a[3]), "r"(b0), "r"(b1));
}

__device__ __forceinline__ void ldsm4(uint32_t* r, uint32_t addr) {
    asm volatile("ldmatrix.sync.aligned.m8n8.x4.shared.b16 "
                 "{%0,%1,%2,%3}, [%4];"
                 : "=r"(r[0]), "=r"(r[1]), "=r"(r[2]), "=r"(r[3]) : "r"(addr));
}

__device__ __forceinline__ void ldsm4t(uint32_t* r, uint32_t addr) {
    asm volatile("ldmatrix.sync.aligned.m8n8.x4.trans.shared.b16 "
                 "{%0,%1,%2,%3}, [%4];"
                 : "=r"(r[0]), "=r"(r[1]), "=r"(r[2]), "=r"(r[3]) : "r"(addr));
}

__device__ __forceinline__ uint32_t h2pack(float lo, float hi) {
    __half2 h = __floats2half2_rn(lo, hi);
    return *(uint32_t*)&h;
}

// ---------------------------------------------------------------------------
// FP16 tensor-core GEMM: C[M,N] = A[M,K] @ W[N,K]^T (fp16 in, f32 accum)
// 128x128x32 tiles, 256 threads, warp tile 64x32, ldmatrix fragment loads.
// HOUT: write fp16 output (for Q/K/V), else fp32.
// ---------------------------------------------------------------------------
#define TBM 128
#define TBN 128
#define TBK 32
#define TSTH 40
#define ASZH (TBM * TSTH)
#define BSZH (TBN * TSTH)
#define NSTG 4
#define GEMM_SMEM (NSTG * (ASZH + BSZH) * 2)   // 81920 B

template<bool HOUT>
__global__ __launch_bounds__(256) void gemm_f16(
    const __half* __restrict__ A, const __half* __restrict__ W,
    float* __restrict__ C, __half* __restrict__ Ch, int M, int N, int K)
{
    extern __shared__ __half smem_h[];
    __half* SA = smem_h;
    __half* SB = smem_h + NSTG * ASZH;

    const int tid  = threadIdx.x;
    const int lane = tid & 31;
    const int wid  = tid >> 5;
    const int wm   = (wid & 1) * 64;
    const int wn   = (wid >> 1) * 32;
    const int g    = lane >> 2;
    const int t    = lane & 3;

    const int bm = blockIdx.y * TBM;
    const int bn = blockIdx.x * TBN;

    const uint32_t sa_base = (uint32_t)__cvta_generic_to_shared(SA);
    const uint32_t sb_base = (uint32_t)__cvta_generic_to_shared(SB);

    const int r0 = tid >> 2;               // 0..63 (+64*i)
    const int u0 = (tid & 3) * 8;          // 4 units x 16B = 32 halves = TBK

    const int lrow = lane & 15;
    const int lcol = (lane >> 4) * 8;

    float acc[4][4][4];
#pragma unroll
    for (int mt = 0; mt < 4; mt++)
#pragma unroll
        for (int nt = 0; nt < 4; nt++)
#pragma unroll
            for (int i = 0; i < 4; i++) acc[mt][nt][i] = 0.f;

    const int nk = K / TBK;

    auto load_stage = [&](int kt) {
        const int s  = kt % NSTG;
        const int ke = kt * TBK;
#pragma unroll
        for (int i = 0; i < 2; i++) {
            int row = r0 + 64 * i;
            cp16(sa_base + (s * ASZH + row * TSTH + u0) * 2,
                 A + (size_t)(bm + row) * K + ke + u0);
            cp16(sb_base + (s * BSZH + row * TSTH + u0) * 2,
                 W + (size_t)(bn + row) * K + ke + u0);
        }
    };

#pragma unroll
    for (int s = 0; s < NSTG - 1; s++) {
        load_stage(s);
        asm volatile("cp.async.commit_group;\n");
    }

    for (int kt = 0; kt < nk; kt++) {
        if (kt + NSTG - 1 < nk) load_stage(kt + NSTG - 1);
        asm volatile("cp.async.commit_group;\n");
        asm volatile("cp.async.wait_group %0;\n" :: "n"(NSTG - 1));
        __syncthreads();

        const int s = kt % NSTG;
#pragma unroll
        for (int ks = 0; ks < 2; ks++) {
            uint32_t af[4][4], bf[4][2];
#pragma unroll
            for (int mt = 0; mt < 4; mt++) {
                uint32_t addr = sa_base +
                    (s * ASZH + (wm + mt * 16 + lrow) * TSTH + ks * 16 + lcol) * 2;
                ldsm4(af[mt], addr);
            }
#pragma unroll
            for (int np = 0; np < 2; np++) {
                uint32_t bq[4];
                uint32_t addr = sb_base +
                    (s * BSZH + (wn + np * 16 + lrow) * TSTH + ks * 16 + lcol) * 2;
                ldsm4(bq, addr);
                bf[2 * np][0] = bq[0]; bf[2 * np][1] = bq[2];
                bf[2 * np + 1][0] = bq[1]; bf[2 * np + 1][1] = bq[3];
            }
#pragma unroll
            for (int mt = 0; mt < 4; mt++)
#pragma unroll
                for (int nt = 0; nt < 4; nt++)
                    mma_f16(acc[mt][nt], af[mt], bf[nt][0], bf[nt][1]);
        }
        __syncthreads();
    }

    if (HOUT) {
        __half* Cp = Ch + (size_t)(bm + wm + g) * N + bn + wn + 2 * t;
#pragma unroll
        for (int mt = 0; mt < 4; mt++) {
#pragma unroll
            for (int nt = 0; nt < 4; nt++) {
                uint32_t v0 = h2pack(acc[mt][nt][0], acc[mt][nt][1]);
                uint32_t v1 = h2pack(acc[mt][nt][2], acc[mt][nt][3]);
                *(uint32_t*)(Cp + (size_t)(mt * 16) * N + nt * 8) = v0;
                *(uint32_t*)(Cp + (size_t)(mt * 16 + 8) * N + nt * 8) = v1;
            }
        }
    } else {
        float* Cp = C + (size_t)(bm + wm + g) * N + bn + wn + 2 * t;
#pragma unroll
        for (int mt = 0; mt < 4; mt++) {
#pragma unroll
            for (int nt = 0; nt < 4; nt++) {
                float* p0 = Cp + (size_t)(mt * 16) * N + nt * 8;
                *(float2*)p0 = make_float2(acc[mt][nt][0], acc[mt][nt][1]);
                float* p1 = p0 + (size_t)8 * N;
                *(float2*)p1 = make_float2(acc[mt][nt][2], acc[mt][nt][3]);
            }
        }
    }
}

// ---------------------------------------------------------------------------
// FP16 tensor-core causal flash attention.
// q-tile 128 (8 warps x 16 rows), k-tile 64, d=64.
// FIXED loaders: a d=64 fp16 row = 128B = EIGHT 16B units (R9 loaded four).
// ---------------------------------------------------------------------------
#define AQ   128
#define KT_  64
#define AST  72                              // smem row stride (halves)
#define QSZ  (AQ * AST)
#define KVSZ (KT_ * AST)
#define ATTN_SMEM ((QSZ + 2 * 2 * KVSZ) * 2) // 55296 B

__global__ __launch_bounds__(256) void attn_mma(
    const __half* __restrict__ Q, const __half* __restrict__ K,
    const __half* __restrict__ V, __half* __restrict__ O)
{
    extern __shared__ __half sm[];
    const uint32_t sbase = (uint32_t)__cvta_generic_to_shared(sm);
    const uint32_t qs = sbase;

    const int tid  = threadIdx.x;
    const int lane = tid & 31;
    const int ws   = tid >> 5;
    const int g    = lane >> 2;
    const int t    = lane & 3;
    const int lrow = lane & 15;
    const int lcol = (lane >> 4) * 8;

    const int bh = blockIdx.y;
    const int b  = bh >> 4;
    const int h  = bh & 15;
    const int qm = gridDim.x - 1 - blockIdx.x;
    const int q0 = qm * AQ;

    const __half* Qg = Q + (size_t)b * S_ * D_ + (size_t)h * DK_;
    const __half* Kg = K + (size_t)b * S_ * D_ + (size_t)h * DK_;
    const __half* Vg = V + (size_t)b * S_ * D_ + (size_t)h * DK_;
    __half*       Og = O + (size_t)b * S_ * D_ + (size_t)h * DK_;

    // K/V tile: 64 rows x 8 units = 512 cp per tensor -> 2 iterations.
    auto load_kv = [&](int s, int kt) {
        const int k0 = kt * KT_;
#pragma unroll
        for (int i = 0; i < 2; i++) {
            int idx = tid + 256 * i;             // 0..511
            int row = idx >> 3;                  // 0..63
            int u   = (idx & 7) * 8;             // 0..56 halves
            uint32_t kdst = sbase + (QSZ + s * 2 * KVSZ + row * AST + u) * 2;
            cp16(kdst, Kg + (size_t)(k0 + row) * D_ + u);
            cp16(kdst + KVSZ * 2, Vg + (size_t)(k0 + row) * D_ + u);
        }
    };

    // Q tile: 128 rows x 8 units = 1024 cp -> 4 iterations.
#pragma unroll
    for (int i = 0; i < 4; i++) {
        int idx = tid + 256 * i;                 // 0..1023
        int row = idx >> 3;                      // 0..127
        int u   = (idx & 7) * 8;
        cp16(qs + (row * AST + u) * 2, Qg + (size_t)(q0 + row) * D_ + u);
    }
    load_kv(0, 0);
    asm volatile("cp.async.commit_group;\n");
    asm volatile("cp.async.wait_group 0;\n");
    __syncthreads();

    uint32_t qf[4][4];
#pragma unroll
    for (int kc = 0; kc < 4; kc++)
        ldsm4(qf[kc], qs + ((ws * 16 + lrow) * AST + kc * 16 + lcol) * 2);

    float o[8][4];
#pragma unroll
    for (int nt = 0; nt < 8; nt++)
#pragma unroll
        for (int i = 0; i < 4; i++) o[nt][i] = 0.f;
    float mi0 = -1e30f, mi1 = -1e30f, li0 = 0.f, li1 = 0.f;

    const int last = q0 / 64 + 1;
    const float sc = 0.125f;
    const int qrow0 = q0 + ws * 16 + g;
    const int qrow1 = qrow0 + 8;

    for (int kt = 0; kt <= last; kt++) {
        const int k0 = kt * KT_;
        if (kt < last) {
            load_kv((kt + 1) & 1, kt + 1);
            asm volatile("cp.async.commit_group;\n");
        }
        if (kt > 0) {
            if (kt < last) asm volatile("cp.async.wait_group 1;\n");
            else           asm volatile("cp.async.wait_group 0;\n");
        }
        __syncthreads();

        const uint32_t ks_ = sbase + (QSZ + (kt & 1) * 2 * KVSZ) * 2;
        const uint32_t vs_ = ks_ + KVSZ * 2;

        float s[8][4];
#pragma unroll
        for (int nt = 0; nt < 8; nt++)
#pragma unroll
            for (int i = 0; i < 4; i++) s[nt][i] = 0.f;
#pragma unroll
        for (int kc = 0; kc < 4; kc++) {
#pragma unroll
            for (int np = 0; np < 4; np++) {
                uint32_t bq[4];
                ldsm4(bq, ks_ + ((np * 16 + lrow) * AST + kc * 16 + lcol) * 2);
                mma_f16(s[2 * np],     qf[kc], bq[0], bq[2]);
                mma_f16(s[2 * np + 1], qf[kc], bq[1], bq[3]);
            }
        }

        if (k0 >= q0) {
#pragma unroll
            for (int nt = 0; nt < 8; nt++) {
                int c0 = k0 + nt * 8 + 2 * t;
                s[nt][0] = (c0     <= qrow0) ? s[nt][0] * sc : -1e30f;
                s[nt][1] = (c0 + 1 <= qrow0) ? s[nt][1] * sc : -1e30f;
                s[nt][2] = (c0     <= qrow1) ? s[nt][2] * sc : -1e30f;
                s[nt][3] = (c0 + 1 <= qrow1) ? s[nt][3] * sc : -1e30f;
            }
        } else {
#pragma unroll
            for (int nt = 0; nt < 8; nt++)
#pragma unroll
                for (int i = 0; i < 4; i++) s[nt][i] *= sc;
        }

        float rm0 = -1e30f, rm1 = -1e30f;
#pragma unroll
        for (int nt = 0; nt < 8; nt++) {
            rm0 = fmaxf(rm0, fmaxf(s[nt][0], s[nt][1]));
            rm1 = fmaxf(rm1, fmaxf(s[nt][2], s[nt][3]));
        }
#pragma unroll
        for (int off = 1; off <= 2; off <<= 1) {
            rm0 = fmaxf(rm0, __shfl_xor_sync(0xffffffffu, rm0, off));
            rm1 = fmaxf(rm1, __shfl_xor_sync(0xffffffffu, rm1, off));
        }
        float mn0 = fmaxf(mi0, rm0), mn1 = fmaxf(mi1, rm1);
        float rs0 = 0.f, rs1 = 0.f;
#pragma unroll
        for (int nt = 0; nt < 8; nt++) {
            s[nt][0] = __expf(s[nt][0] - mn0);
            s[nt][1] = __expf(s[nt][1] - mn0);
            s[nt][2] = __expf(s[nt][2] - mn1);
            s[nt][3] = __expf(s[nt][3] - mn1);
            rs0 += s[nt][0] + s[nt][1];
            rs1 += s[nt][2] + s[nt][3];
        }
#pragma unroll
        for (int off = 1; off <= 2; off <<= 1) {
            rs0 += __shfl_xor_sync(0xffffffffu, rs0, off);
            rs1 += __shfl_xor_sync(0xffffffffu, rs1, off);
        }
        float al0 = __expf(mi0 - mn0), al1 = __expf(mi1 - mn1);
        li0 = li0 * al0 + rs0;  li1 = li1 * al1 + rs1;
        mi0 = mn0;  mi1 = mn1;
#pragma unroll
        for (int nt = 0; nt < 8; nt++) {
            o[nt][0] *= al0; o[nt][1] *= al0;
            o[nt][2] *= al1; o[nt][3] *= al1;
        }

        uint32_t pa[4][4];
#pragma unroll
        for (int kc = 0; kc < 4; kc++) {
            pa[kc][0] = h2pack(s[2 * kc][0],     s[2 * kc][1]);
            pa[kc][1] = h2pack(s[2 * kc][2],     s[2 * kc][3]);
            pa[kc][2] = h2pack(s[2 * kc + 1][0], s[2 * kc + 1][1]);
            pa[kc][3] = h2pack(s[2 * kc + 1][2], s[2 * kc + 1][3]);
        }

        const int trow = (lane & 7) + ((lane & 16) ? 8 : 0);
        const int tcol = (lane & 8) ? 8 : 0;
#pragma unroll
        for (int kc = 0; kc < 4; kc++) {
#pragma unroll
            for (int dp = 0; dp < 4; dp++) {
                uint32_t rv[4];
                ldsm4t(rv, vs_ + ((kc * 16 + trow) * AST + dp * 16 + tcol) * 2);
                mma_f16(o[2 * dp],     pa[kc], rv[0], rv[2]);
                mma_f16(o[2 * dp + 1], pa[kc], rv[1], rv[3]);
            }
        }
        __syncthreads();
    }

    const float iv0 = 1.0f / li0, iv1 = 1.0f / li1;
#pragma unroll
    for (int nt = 0; nt < 8; nt++) {
        int col = nt * 8 + 2 * t;
        uint32_t v0 = h2pack(o[nt][0] * iv0, o[nt][1] * iv0);
        uint32_t v1 = h2pack(o[nt][2] * iv1, o[nt][3] * iv1);
        *(uint32_t*)(Og + (size_t)qrow0 * D_ + col) = v0;
        *(uint32_t*)(Og + (size_t)qrow1 * D_ + col) = v1;
    }
}

// ---------------------------------------------------------------------------
// Launch
// ---------------------------------------------------------------------------
extern "C" void kernel_launch(void* const* d_in, const int* in_sizes, int n_in,
                              void* d_out, int out_size)
{
    const float* x  = (const float*)d_in[0];
    const float* WQ = (const float*)d_in[1];
    const float* WK = (const float*)d_in[2];
    const float* WV = (const float*)d_in[3];
    const float* WO = (const float*)d_in[4];
    float* out = (float*)d_out;

    __half *Xh, *Wh, *Qh, *Kh, *Vh, *Ah;
    cudaGetSymbolAddress((void**)&Xh, g_Xh);
    cudaGetSymbolAddress((void**)&Wh, g_Wh);
    cudaGetSymbolAddress((void**)&Qh, g_Qh);
    cudaGetSymbolAddress((void**)&Kh, g_Kh);
    cudaGetSymbolAddress((void**)&Vh, g_Vh);
    cudaGetSymbolAddress((void**)&Ah, g_Ah);

    cudaFuncSetAttribute(gemm_f16<true>,
                         cudaFuncAttributeMaxDynamicSharedMemorySize, GEMM_SMEM);
    cudaFuncSetAttribute(gemm_f16<false>,
                         cudaFuncAttributeMaxDynamicSharedMemorySize, GEMM_SMEM);
    cudaFuncSetAttribute(attn_mma,
                         cudaFuncAttributeMaxDynamicSharedMemorySize, ATTN_SMEM);

    const int M   = B_ * S_;
    const int nX8 = (M * D_) / 8;
    const int nW8 = (D_ * D_) / 8;

    cvt_f16_k<<<(nX8 + 255) / 256, 256>>>((const float4*)x, (uint4*)Xh, nX8);
    cvt_f16_k<<<(nW8 + 255) / 256, 256>>>((const float4*)WQ, (uint4*)(Wh + 0 * (size_t)D_ * D_), nW8);
    cvt_f16_k<<<(nW8 + 255) / 256, 256>>>((const float4*)WK, (uint4*)(Wh + 1 * (size_t)D_ * D_), nW8);
    cvt_f16_k<<<(nW8 + 255) / 256, 256>>>((const float4*)WV, (uint4*)(Wh + 2 * (size_t)D_ * D_), nW8);
    cvt_f16_k<<<(nW8 + 255) / 256, 256>>>((const float4*)WO, (uint4*)(Wh + 3 * (size_t)D_ * D_), nW8);

    dim3 gg(D_ / TBN, M / TBM);
    gemm_f16<true><<<gg, 256, GEMM_SMEM>>>(Xh, Wh + 0 * (size_t)D_ * D_, nullptr, Qh, M, D_, D_);
    gemm_f16<true><<<gg, 256, GEMM_SMEM>>>(Xh, Wh + 1 * (size_t)D_ * D_, nullptr, Kh, M, D_, D_);
    gemm_f16<true><<<gg, 256, GEMM_SMEM>>>(Xh, Wh + 2 * (size_t)D_ * D_, nullptr, Vh, M, D_, D_);

    attn_mma<<<dim3(S_ / AQ, B_ * H_), 256, ATTN_SMEM>>>(Qh, Kh, Vh, Ah);

    gemm_f16<false><<<gg, 256, GEMM_SMEM>>>(Ah, Wh + 3 * (size_t)D_ * D_, out, nullptr, M, D_, D_);
}